// round 12
// baseline (speedup 1.0000x reference)
#include <cuda_runtime.h>
#include <cstdint>

// Problem constants
#define TT    4096     // sequence length T
#define TM1   4095     // T-1 steps
#define EE    512      // embedding dim E
#define HH    1024     // hidden dim H
#define G4    4096     // 4*H
#define CC    1221     // output classes C
#define NLSTM 128      // recurrence CTAs
#define NHELP 20       // helper CTAs (GEMM overlap)
#define NCOPY 16       // h replica count (poll-traffic dedup) — ONLY change vs R9

#define XG_MT 32       // xg M tiles (4095 -> 32x128)
#define XG_NT 32       // xg N tiles (4096/128)
#define XG_TILES (XG_MT * XG_NT)
#define OUT_MT 32
#define OUT_NT 10      // ceil(1221/128)
#define OUT_TILES (OUT_MT * OUT_NT)

typedef unsigned long long u64;

#define CANARY 0x7fc0deadu   // qNaN payload: h in (-1,1) can never equal it
#define COPYSZ ((size_t)TM1 * HH)

// ---------------- scratch (static device globals; no allocation allowed) ----
__device__ float    g_emb[(size_t)TT * EE];        // gathered embeddings  (8 MB)
__device__ float    g_bias4h[G4];                  // b_ih + b_hh + last@W_ih[:,E:]
__device__ float    g_xg[(size_t)TM1 * G4];        // input gates (67 MB, JIT by helpers)
__device__ float    g_hsA[NCOPY * COPYSZ];         // hidden states, 16 replicas (268 MB)
__device__ unsigned g_work;                        // helper work-steal counter
__device__ unsigned g_xgcnt[XG_MT];                // completed N-tiles per xg M-tile
__device__ unsigned g_xgflag[XG_MT];               // xg M-tile ready flags

// ---------------- helpers ---------------------------------------------------
__device__ __forceinline__ u64 fma2(u64 a, u64 b, u64 c) {
    u64 d;
    asm("fma.rn.f32x2 %0, %1, %2, %3;" : "=l"(d) : "l"(a), "l"(b), "l"(c));
    return d;
}
__device__ __forceinline__ u64 pack2(float lo, float hi) {
    u64 r;
    asm("mov.b64 %0, {%1, %2};" : "=l"(r) : "f"(lo), "f"(hi));
    return r;
}
__device__ __forceinline__ float2 unpack2(u64 v) {
    float2 r;
    asm("mov.b64 {%0, %1}, %2;" : "=f"(r.x), "=f"(r.y) : "l"(v));
    return r;
}
__device__ __forceinline__ uint4 ld_vol4(const void* p) {
    uint4 v;
    asm volatile("ld.volatile.global.v4.u32 {%0,%1,%2,%3}, [%4];"
                 : "=r"(v.x), "=r"(v.y), "=r"(v.z), "=r"(v.w)
                 : "l"(p) : "memory");
    return v;
}
__device__ __forceinline__ void st_vol4(float* p, float4 v) {
    asm volatile("st.volatile.global.v4.f32 [%0], {%1,%2,%3,%4};"
                 :: "l"(p), "f"(v.x), "f"(v.y), "f"(v.z), "f"(v.w) : "memory");
}
__device__ __forceinline__ bool bad4(uint4 v) {
    return (v.x == CANARY) | (v.y == CANARY) | (v.z == CANARY) | (v.w == CANARY);
}
__device__ __forceinline__ unsigned ld_acq(const unsigned* p) {
    unsigned v;
    asm volatile("ld.acquire.gpu.global.u32 %0, [%1];" : "=r"(v) : "l"(p) : "memory");
    return v;
}
__device__ __forceinline__ void wait_flag(const unsigned* p) {
    while (ld_acq(p) == 0u) { }
}

// ---------------- gather + replica canary fill + control reset ---------------
__global__ void k_gather(const int* __restrict__ x, const float* __restrict__ tab) {
    int t   = blockIdx.x;
    int tid = threadIdx.x;
    if (blockIdx.x == 0) {
        if (tid == 0) g_work = 0u;
        if (tid < XG_MT) { g_xgcnt[tid] = 0u; g_xgflag[tid] = 0u; }
    }
    if (tid < 128) {
        int row = x[t];
        float4 v = *(const float4*)(tab + (size_t)row * EE + tid * 4);
        *(float4*)(g_emb + (size_t)t * EE + tid * 4) = v;
    }
    size_t i = (size_t)blockIdx.x * 256 + tid;          // uint4 index within a copy
    if (i < COPYSZ / 4) {
        uint4 c4 = make_uint4(CANARY, CANARY, CANARY, CANARY);
#pragma unroll
        for (int c = 0; c < NCOPY; c++)
            *(uint4*)((unsigned*)g_hsA + c * COPYSZ + i * 4) = c4;
    }
}

// ---------------- bias vector: b_ih + b_hh + last_emb @ W_ih[:, E:].T --------
__global__ void k_bias(const float* __restrict__ W_ih,
                       const float* __restrict__ b_ih,
                       const float* __restrict__ b_hh) {
    int w = threadIdx.x >> 5, lane = threadIdx.x & 31;
    int g = blockIdx.x * 8 + w;
    const float* wrow = W_ih + (size_t)g * (2 * EE) + EE;
    const float* le   = g_emb + (size_t)(TT - 1) * EE;
    float s = 0.f;
#pragma unroll
    for (int i = 0; i < 4; i++) {
        float4 a = *(const float4*)(wrow + i * 128 + lane * 4);
        float4 b = *(const float4*)(le   + i * 128 + lane * 4);
        s += a.x * b.x + a.y * b.y + a.z * b.z + a.w * b.w;
    }
#pragma unroll
    for (int off = 16; off; off >>= 1) s += __shfl_xor_sync(0xffffffffu, s, off);
    if (lane == 0) g_bias4h[g] = s + b_ih[g] + b_hh[g];
}

// ---------------- one 128x128 SGEMM tile: C = A * B^T + bias -----------------
// POLLA: A elements are NaN-canary dataflow values (retry until written).
template<bool POLLA>
__device__ void sgemm_tile(
    const float* A, int lda,
    const float* __restrict__ B, int ldb,
    const float* __restrict__ bias,
    float* C, int ldc,
    int M, int N, int K, int row0, int col0)
{
    __shared__ __align__(16) float As[16][128];
    __shared__ __align__(16) float Bs[16][128];
    int tid = threadIdx.x;
    int tx = tid & 15, ty = tid >> 4;

    u64 acc[8][4];
#pragma unroll
    for (int m = 0; m < 8; m++)
#pragma unroll
        for (int n2 = 0; n2 < 4; n2++) acc[m][n2] = 0ull;

    for (int k0 = 0; k0 < K; k0 += 16) {
#pragma unroll
        for (int li = tid; li < 512; li += 256) {
            int r = li >> 2, c4 = (li & 3) << 2;
            float4 v = make_float4(0.f, 0.f, 0.f, 0.f);
            int gr = row0 + r;
            if (gr < M) {
                const void* src = A + (size_t)gr * lda + k0 + c4;
                if (POLLA) {
                    uint4 u;
                    do { u = ld_vol4(src); } while (bad4(u));
                    v = *(float4*)&u;
                } else {
                    v = *(const float4*)src;
                }
            }
            As[c4][r] = v.x; As[c4 + 1][r] = v.y; As[c4 + 2][r] = v.z; As[c4 + 3][r] = v.w;
            float4 wv = make_float4(0.f, 0.f, 0.f, 0.f);
            int gn = col0 + r;
            if (gn < N) wv = *(const float4*)(B + (size_t)gn * ldb + k0 + c4);
            Bs[c4][r] = wv.x; Bs[c4 + 1][r] = wv.y; Bs[c4 + 2][r] = wv.z; Bs[c4 + 3][r] = wv.w;
        }
        __syncthreads();
#pragma unroll
        for (int k = 0; k < 16; k++) {
            float4 a0 = *(const float4*)&As[k][ty * 8];
            float4 a1 = *(const float4*)&As[k][ty * 8 + 4];
            ulonglong2 b0 = *(const ulonglong2*)&Bs[k][tx * 8];
            ulonglong2 b1 = *(const ulonglong2*)&Bs[k][tx * 8 + 4];
            float av[8] = {a0.x, a0.y, a0.z, a0.w, a1.x, a1.y, a1.z, a1.w};
            u64 bv[4] = {b0.x, b0.y, b1.x, b1.y};
#pragma unroll
            for (int m = 0; m < 8; m++) {
                u64 am = pack2(av[m], av[m]);
#pragma unroll
                for (int n2 = 0; n2 < 4; n2++)
                    acc[m][n2] = fma2(am, bv[n2], acc[m][n2]);
            }
        }
        __syncthreads();
    }
#pragma unroll
    for (int m = 0; m < 8; m++) {
        int gr = row0 + ty * 8 + m;
        if (gr >= M) continue;
#pragma unroll
        for (int n2 = 0; n2 < 4; n2++) {
            float2 s = unpack2(acc[m][n2]);
            int gc = col0 + tx * 8 + n2 * 2;
            if (gc < N)     C[(size_t)gr * ldc + gc]     = s.x + bias[gc];
            if (gc + 1 < N) C[(size_t)gr * ldc + gc + 1] = s.y + bias[gc + 1];
        }
    }
}

// ---------------- helper role: JIT xg GEMM, then trailing out GEMM -----------
__device__ void helper_role(const float* __restrict__ W_ih,
                            const float* __restrict__ W_out,
                            const float* __restrict__ b_out,
                            float* __restrict__ out) {
    __shared__ unsigned s_item;
    int tid = threadIdx.x;
    for (;;) {
        if (tid == 0) s_item = atomicAdd(&g_work, 1u);
        __syncthreads();
        unsigned item = s_item;
        __syncthreads();
        if (item < XG_TILES) {
            // xg tile, M-tile-major so rows appear in consumption order
            int mt = item >> 5, nt = item & 31;
            sgemm_tile<false>(g_emb, EE, W_ih, 2 * EE, g_bias4h,
                              g_xg, G4, TM1, G4, EE, mt * 128, nt * 128);
            __threadfence();
            __syncthreads();
            if (tid == 0) {
                unsigned old;
                asm volatile("atom.acq_rel.gpu.global.add.u32 %0, [%1], 1;"
                             : "=r"(old) : "l"(&g_xgcnt[mt]) : "memory");
                if (old == XG_NT - 1)
                    asm volatile("st.release.gpu.global.u32 [%0], %1;"
                                 :: "l"(&g_xgflag[mt]), "r"(1u) : "memory");
            }
            __syncthreads();
        } else if (item < XG_TILES + OUT_TILES) {
            // out tile; A loads canary-poll h rows (self-throttles to frontier)
            int idx = (int)item - XG_TILES;
            int mt = idx / OUT_NT, nt = idx % OUT_NT;
            const float* hsrc = g_hsA + (size_t)(mt & (NCOPY - 1)) * COPYSZ;
            sgemm_tile<true>(hsrc, HH, W_out, HH, b_out,
                             out, CC, TM1, CC, HH, mt * 128, nt * 128);
            __syncthreads();
        } else {
            break;
        }
    }
}

// ---------------- recurrence role (exact R9 structure; NCOPY=16) -------------
__device__ void lstm_role(const float* __restrict__ W_hh) {
    __shared__ __align__(16) float h_s[2][HH];
    __shared__ __align__(16) float s_h[2][8];      // per-warp h staging (double buf)
    int tid = threadIdx.x;
    int w = tid >> 5, lane = tid & 31;
    int j = blockIdx.x * 8 + w;
    const float* mycopy = g_hsA + (size_t)(blockIdx.x & (NCOPY - 1)) * COPYSZ;

    // This warp's W_hh rows in registers: 4 gates x 32 k per lane (f32x2 pairs)
    ulonglong2 wr[4][8];
#pragma unroll
    for (int g = 0; g < 4; g++) {
        const float* base = W_hh + (size_t)(g * HH + j) * HH + lane * 4;
#pragma unroll
        for (int i = 0; i < 8; i++)
            wr[g][i] = *(const ulonglong2*)(base + i * 128);
    }

    float c = 0.f;
    float xgv = 0.f;
    if (lane < 4) {                       // t = 0 prefetch (gated on xg tile 0)
        wait_flag(&g_xgflag[0]);
        xgv = g_xg[(size_t)lane * HH + j];
    }

    for (int t = 0; t < TM1; t++) {
        float* buf = h_s[t & 1];

        // stage own 16B chunk of h_{t-1} from my replica (canary poll).
        // Chunks are published as single 16B stores -> all-or-nothing visibility.
        if (t == 0) {
            *(float4*)&buf[tid * 4] = make_float4(0.f, 0.f, 0.f, 0.f);
        } else {
            const void* src = mycopy + (size_t)(t - 1) * HH + tid * 4;
            uint4 v;
            do {
                v = ld_vol4(src);
            } while (bad4(v));
            *(uint4*)&buf[tid * 4] = v;
        }
        __syncthreads();

        // 4 gate dot products over K=1024, f32x2 FMAs
        u64 acc[4] = {0ull, 0ull, 0ull, 0ull};
#pragma unroll
        for (int i = 0; i < 8; i++) {
            ulonglong2 h2 = *(const ulonglong2*)&buf[i * 128 + lane * 4];
#pragma unroll
            for (int g = 0; g < 4; g++) {
                acc[g] = fma2(wr[g][i].x, h2.x, acc[g]);
                acc[g] = fma2(wr[g][i].y, h2.y, acc[g]);
            }
        }
        float r0, r1, r2, r3;
        { float2 s = unpack2(acc[0]); r0 = s.x + s.y; }
        { float2 s = unpack2(acc[1]); r1 = s.x + s.y; }
        { float2 s = unpack2(acc[2]); r2 = s.x + s.y; }
        { float2 s = unpack2(acc[3]); r3 = s.x + s.y; }
#pragma unroll
        for (int off = 16; off; off >>= 1) {
            r0 += __shfl_xor_sync(0xffffffffu, r0, off);
            r1 += __shfl_xor_sync(0xffffffffu, r1, off);
            r2 += __shfl_xor_sync(0xffffffffu, r2, off);
            r3 += __shfl_xor_sync(0xffffffffu, r3, off);
        }

        // Activations: lanes 0..3 handle gates i,f,g,o. tanh(x)=2*sigmoid(2x)-1
        float rv = (lane == 0) ? r0 : (lane == 1) ? r1 : (lane == 2) ? r2 : r3;
        float s  = rv + xgv;
        float si = (lane == 2) ? (s + s) : s;
        float a  = __fdividef(1.f, 1.f + __expf(-si));
        if (lane == 2) a = 2.f * a - 1.f;
        float gi = __shfl_sync(0xffffffffu, a, 0);
        float gf = __shfl_sync(0xffffffffu, a, 1);
        float gg = __shfl_sync(0xffffffffu, a, 2);
        float go = __shfl_sync(0xffffffffu, a, 3);
        c = gf * c + gi * gg;
        float tc = __fdividef(2.f, 1.f + __expf(-2.f * c)) - 1.f;
        float hv = go * tc;

        // aggregate the CTA's 8 h values, publish each replica-chunk as ONE
        // 16B store (all-or-nothing visibility for consumers); 32 stores =
        // one warp-0 instruction
        if (lane == 0) s_h[t & 1][w] = hv;
        __syncthreads();
        if (tid < 2 * NCOPY) {
            int rep = tid >> 1, ch = tid & 1;
            float4 val = *(float4*)&s_h[t & 1][ch * 4];
            float* dst = (float*)g_hsA + (size_t)rep * COPYSZ
                       + (size_t)t * HH + blockIdx.x * 8 + ch * 4;
            st_vol4(dst, val);
        }

        // prefetch next step's xg (gate on tile flag at 128-step boundaries)
        int tn = t + 1;
        if (tn < TM1 && lane < 4) {
            if ((tn & 127) == 0) wait_flag(&g_xgflag[tn >> 7]);
            xgv = g_xg[(size_t)tn * G4 + lane * HH + j];
        }
    }
}

// ---------------- fused persistent kernel ------------------------------------
__global__ __launch_bounds__(256, 1) void k_main(
    const float* __restrict__ W_ih,
    const float* __restrict__ W_hh,
    const float* __restrict__ W_out,
    const float* __restrict__ b_out,
    float* __restrict__ out)
{
    if (blockIdx.x < NLSTM) lstm_role(W_hh);
    else                    helper_role(W_ih, W_out, b_out, out);
}

// ---------------- launch ------------------------------------------------------
extern "C" void kernel_launch(void* const* d_in, const int* in_sizes, int n_in,
                              void* d_out, int out_size) {
    const int*   x     = (const int*)d_in[0];
    const float* table = (const float*)d_in[1];
    const float* W_ih  = (const float*)d_in[2];
    const float* W_hh  = (const float*)d_in[3];
    const float* b_ih  = (const float*)d_in[4];
    const float* b_hh  = (const float*)d_in[5];
    const float* W_out = (const float*)d_in[6];
    const float* b_out = (const float*)d_in[7];
    float* out = (float*)d_out;
    (void)in_sizes; (void)n_in; (void)out_size;

    k_gather<<<TT, 256>>>(x, table);            // gather + 16-replica canary + ctrl reset
    k_bias<<<G4 / 8, 256>>>(W_ih, b_ih, b_hh);
    k_main<<<NLSTM + NHELP, 256>>>(W_ih, W_hh, W_out, b_out, out);
}

// round 13
// speedup vs baseline: 1.5345x; 1.5345x over previous
#include <cuda_runtime.h>
#include <cstdint>

// Problem constants
#define TT    4096     // sequence length T
#define TM1   4095     // T-1 steps
#define EE    512      // embedding dim E
#define HH    1024     // hidden dim H
#define G4    4096     // 4*H
#define CC    1221     // output classes C
#define NLSTM 128      // recurrence CTAs
#define NHELP 20       // helper CTAs (GEMM overlap)
#define NCOPY 8        // h replica count — CONFIRMED optimum (4: -420cyc, 8: -180, 16: inverts)

#define XG_MT 32       // xg M tiles (4095 -> 32x128)
#define XG_NT 32       // xg N tiles (4096/128)
#define XG_TILES (XG_MT * XG_NT)
#define OUT_MT 32
#define OUT_NT 10      // ceil(1221/128)
#define OUT_TILES (OUT_MT * OUT_NT)

typedef unsigned long long u64;

#define CANARY 0x7fc0deadu   // qNaN payload: h in (-1,1) can never equal it
#define COPYSZ ((size_t)TM1 * HH)

// ---------------- scratch (static device globals; no allocation allowed) ----
__device__ float    g_emb[(size_t)TT * EE];        // gathered embeddings  (8 MB)
__device__ float    g_bias4h[G4];                  // b_ih + b_hh + last@W_ih[:,E:]
__device__ float    g_xg[(size_t)TM1 * G4];        // input gates (67 MB, JIT by helpers)
__device__ float    g_hsA[NCOPY * COPYSZ];         // hidden states, 8 replicas (134 MB)
__device__ unsigned g_work;                        // helper work-steal counter
__device__ unsigned g_xgcnt[XG_MT];                // completed N-tiles per xg M-tile
__device__ unsigned g_xgflag[XG_MT];               // xg M-tile ready flags

// ---------------- helpers ---------------------------------------------------
__device__ __forceinline__ u64 fma2(u64 a, u64 b, u64 c) {
    u64 d;
    asm("fma.rn.f32x2 %0, %1, %2, %3;" : "=l"(d) : "l"(a), "l"(b), "l"(c));
    return d;
}
__device__ __forceinline__ u64 pack2(float lo, float hi) {
    u64 r;
    asm("mov.b64 %0, {%1, %2};" : "=l"(r) : "f"(lo), "f"(hi));
    return r;
}
__device__ __forceinline__ float2 unpack2(u64 v) {
    float2 r;
    asm("mov.b64 {%0, %1}, %2;" : "=f"(r.x), "=f"(r.y) : "l"(v));
    return r;
}
__device__ __forceinline__ uint4 ld_vol4(const void* p) {
    uint4 v;
    asm volatile("ld.volatile.global.v4.u32 {%0,%1,%2,%3}, [%4];"
                 : "=r"(v.x), "=r"(v.y), "=r"(v.z), "=r"(v.w)
                 : "l"(p) : "memory");
    return v;
}
__device__ __forceinline__ void st_vol4(float* p, float4 v) {
    asm volatile("st.volatile.global.v4.f32 [%0], {%1,%2,%3,%4};"
                 :: "l"(p), "f"(v.x), "f"(v.y), "f"(v.z), "f"(v.w) : "memory");
}
__device__ __forceinline__ bool bad4(uint4 v) {
    return (v.x == CANARY) | (v.y == CANARY) | (v.z == CANARY) | (v.w == CANARY);
}
__device__ __forceinline__ unsigned ld_acq(const unsigned* p) {
    unsigned v;
    asm volatile("ld.acquire.gpu.global.u32 %0, [%1];" : "=r"(v) : "l"(p) : "memory");
    return v;
}
__device__ __forceinline__ void wait_flag(const unsigned* p) {
    while (ld_acq(p) == 0u) { }
}
__device__ __forceinline__ float fast_sig(float x) {      // exact: 1/(1+e^-x)
    return __fdividef(1.f, 1.f + __expf(-x));
}
__device__ __forceinline__ float fast_tanh(float x) {     // exact: 2*sig(2x)-1
    return __fdividef(2.f, 1.f + __expf(-2.f * x)) - 1.f;
}

// ---------------- gather + replica canary fill + control reset ---------------
__global__ void k_gather(const int* __restrict__ x, const float* __restrict__ tab) {
    int t   = blockIdx.x;
    int tid = threadIdx.x;
    if (blockIdx.x == 0) {
        if (tid == 0) g_work = 0u;
        if (tid < XG_MT) { g_xgcnt[tid] = 0u; g_xgflag[tid] = 0u; }
    }
    if (tid < 128) {
        int row = x[t];
        float4 v = *(const float4*)(tab + (size_t)row * EE + tid * 4);
        *(float4*)(g_emb + (size_t)t * EE + tid * 4) = v;
    }
    size_t i = (size_t)blockIdx.x * 256 + tid;          // uint4 index within a copy
    if (i < COPYSZ / 4) {
        uint4 c4 = make_uint4(CANARY, CANARY, CANARY, CANARY);
#pragma unroll
        for (int c = 0; c < NCOPY; c++)
            *(uint4*)((unsigned*)g_hsA + c * COPYSZ + i * 4) = c4;
    }
}

// ---------------- bias vector: b_ih + b_hh + last_emb @ W_ih[:, E:].T --------
__global__ void k_bias(const float* __restrict__ W_ih,
                       const float* __restrict__ b_ih,
                       const float* __restrict__ b_hh) {
    int w = threadIdx.x >> 5, lane = threadIdx.x & 31;
    int g = blockIdx.x * 8 + w;
    const float* wrow = W_ih + (size_t)g * (2 * EE) + EE;
    const float* le   = g_emb + (size_t)(TT - 1) * EE;
    float s = 0.f;
#pragma unroll
    for (int i = 0; i < 4; i++) {
        float4 a = *(const float4*)(wrow + i * 128 + lane * 4);
        float4 b = *(const float4*)(le   + i * 128 + lane * 4);
        s += a.x * b.x + a.y * b.y + a.z * b.z + a.w * b.w;
    }
#pragma unroll
    for (int off = 16; off; off >>= 1) s += __shfl_xor_sync(0xffffffffu, s, off);
    if (lane == 0) g_bias4h[g] = s + b_ih[g] + b_hh[g];
}

// ---------------- one 128x128 SGEMM tile: C = A * B^T + bias -----------------
// POLLA: A elements are NaN-canary dataflow values (retry until written).
template<bool POLLA>
__device__ void sgemm_tile(
    const float* A, int lda,
    const float* __restrict__ B, int ldb,
    const float* __restrict__ bias,
    float* C, int ldc,
    int M, int N, int K, int row0, int col0)
{
    __shared__ __align__(16) float As[16][128];
    __shared__ __align__(16) float Bs[16][128];
    int tid = threadIdx.x;
    int tx = tid & 15, ty = tid >> 4;

    u64 acc[8][4];
#pragma unroll
    for (int m = 0; m < 8; m++)
#pragma unroll
        for (int n2 = 0; n2 < 4; n2++) acc[m][n2] = 0ull;

    for (int k0 = 0; k0 < K; k0 += 16) {
#pragma unroll
        for (int li = tid; li < 512; li += 256) {
            int r = li >> 2, c4 = (li & 3) << 2;
            float4 v = make_float4(0.f, 0.f, 0.f, 0.f);
            int gr = row0 + r;
            if (gr < M) {
                const void* src = A + (size_t)gr * lda + k0 + c4;
                if (POLLA) {
                    uint4 u;
                    do { u = ld_vol4(src); } while (bad4(u));
                    v = *(float4*)&u;
                } else {
                    v = *(const float4*)src;
                }
            }
            As[c4][r] = v.x; As[c4 + 1][r] = v.y; As[c4 + 2][r] = v.z; As[c4 + 3][r] = v.w;
            float4 wv = make_float4(0.f, 0.f, 0.f, 0.f);
            int gn = col0 + r;
            if (gn < N) wv = *(const float4*)(B + (size_t)gn * ldb + k0 + c4);
            Bs[c4][r] = wv.x; Bs[c4 + 1][r] = wv.y; Bs[c4 + 2][r] = wv.z; Bs[c4 + 3][r] = wv.w;
        }
        __syncthreads();
#pragma unroll
        for (int k = 0; k < 16; k++) {
            float4 a0 = *(const float4*)&As[k][ty * 8];
            float4 a1 = *(const float4*)&As[k][ty * 8 + 4];
            ulonglong2 b0 = *(const ulonglong2*)&Bs[k][tx * 8];
            ulonglong2 b1 = *(const ulonglong2*)&Bs[k][tx * 8 + 4];
            float av[8] = {a0.x, a0.y, a0.z, a0.w, a1.x, a1.y, a1.z, a1.w};
            u64 bv[4] = {b0.x, b0.y, b1.x, b1.y};
#pragma unroll
            for (int m = 0; m < 8; m++) {
                u64 am = pack2(av[m], av[m]);
#pragma unroll
                for (int n2 = 0; n2 < 4; n2++)
                    acc[m][n2] = fma2(am, bv[n2], acc[m][n2]);
            }
        }
        __syncthreads();
    }
#pragma unroll
    for (int m = 0; m < 8; m++) {
        int gr = row0 + ty * 8 + m;
        if (gr >= M) continue;
#pragma unroll
        for (int n2 = 0; n2 < 4; n2++) {
            float2 s = unpack2(acc[m][n2]);
            int gc = col0 + tx * 8 + n2 * 2;
            if (gc < N)     C[(size_t)gr * ldc + gc]     = s.x + bias[gc];
            if (gc + 1 < N) C[(size_t)gr * ldc + gc + 1] = s.y + bias[gc + 1];
        }
    }
}

// ---------------- helper role: JIT xg GEMM, then trailing out GEMM -----------
__device__ void helper_role(const float* __restrict__ W_ih,
                            const float* __restrict__ W_out,
                            const float* __restrict__ b_out,
                            float* __restrict__ out) {
    __shared__ unsigned s_item;
    int tid = threadIdx.x;
    for (;;) {
        if (tid == 0) s_item = atomicAdd(&g_work, 1u);
        __syncthreads();
        unsigned item = s_item;
        __syncthreads();
        if (item < XG_TILES) {
            // xg tile, M-tile-major so rows appear in consumption order
            int mt = item >> 5, nt = item & 31;
            sgemm_tile<false>(g_emb, EE, W_ih, 2 * EE, g_bias4h,
                              g_xg, G4, TM1, G4, EE, mt * 128, nt * 128);
            __threadfence();
            __syncthreads();
            if (tid == 0) {
                unsigned old;
                asm volatile("atom.acq_rel.gpu.global.add.u32 %0, [%1], 1;"
                             : "=r"(old) : "l"(&g_xgcnt[mt]) : "memory");
                if (old == XG_NT - 1)
                    asm volatile("st.release.gpu.global.u32 [%0], %1;"
                                 :: "l"(&g_xgflag[mt]), "r"(1u) : "memory");
            }
            __syncthreads();
        } else if (item < XG_TILES + OUT_TILES) {
            // out tile; A loads canary-poll h rows (self-throttles to frontier)
            int idx = (int)item - XG_TILES;
            int mt = idx / OUT_NT, nt = idx % OUT_NT;
            const float* hsrc = g_hsA + (size_t)(mt & (NCOPY - 1)) * COPYSZ;
            sgemm_tile<true>(hsrc, HH, W_out, HH, b_out,
                             out, CC, TM1, CC, HH, mt * 128, nt * 128);
            __syncthreads();
        } else {
            break;
        }
    }
}

// ---------------- recurrence role (R9 structure + pre-reduce xg/all-lane act) -
__device__ void lstm_role(const float* __restrict__ W_hh) {
    __shared__ __align__(16) float h_s[2][HH];
    __shared__ __align__(16) float s_h[2][8];      // per-warp h staging (double buf)
    int tid = threadIdx.x;
    int w = tid >> 5, lane = tid & 31;
    int j = blockIdx.x * 8 + w;
    const float* mycopy = g_hsA + (size_t)(blockIdx.x & (NCOPY - 1)) * COPYSZ;

    // This warp's W_hh rows in registers: 4 gates x 32 k per lane (f32x2 pairs)
    ulonglong2 wr[4][8];
#pragma unroll
    for (int g = 0; g < 4; g++) {
        const float* base = W_hh + (size_t)(g * HH + j) * HH + lane * 4;
#pragma unroll
        for (int i = 0; i < 8; i++)
            wr[g][i] = *(const ulonglong2*)(base + i * 128);
    }

    float c = 0.f;
    float xgv = 0.f;
    if (lane < 4) {                       // t = 0 prefetch (gated on xg tile 0)
        wait_flag(&g_xgflag[0]);
        xgv = g_xg[(size_t)lane * HH + j];
    }

    for (int t = 0; t < TM1; t++) {
        float* buf = h_s[t & 1];

        // stage own 16B chunk of h_{t-1} from my replica (canary poll).
        // Chunks are published as single 16B stores -> all-or-nothing visibility.
        if (t == 0) {
            *(float4*)&buf[tid * 4] = make_float4(0.f, 0.f, 0.f, 0.f);
        } else {
            const void* src = mycopy + (size_t)(t - 1) * HH + tid * 4;
            uint4 v;
            do {
                v = ld_vol4(src);
            } while (bad4(v));
            *(uint4*)&buf[tid * 4] = v;
        }
        __syncthreads();

        // 4 gate dot products over K=1024, f32x2 FMAs
        u64 acc[4] = {0ull, 0ull, 0ull, 0ull};
#pragma unroll
        for (int i = 0; i < 8; i++) {
            ulonglong2 h2 = *(const ulonglong2*)&buf[i * 128 + lane * 4];
#pragma unroll
            for (int g = 0; g < 4; g++) {
                acc[g] = fma2(wr[g][i].x, h2.x, acc[g]);
                acc[g] = fma2(wr[g][i].y, h2.y, acc[g]);
            }
        }
        float r0, r1, r2, r3;
        { float2 s = unpack2(acc[0]); r0 = s.x + s.y; }
        { float2 s = unpack2(acc[1]); r1 = s.x + s.y; }
        { float2 s = unpack2(acc[2]); r2 = s.x + s.y; }
        { float2 s = unpack2(acc[3]); r3 = s.x + s.y; }

        // pre-reduce xg injection: the butterfly sums it in exactly once
        r0 = (lane == 0) ? r0 + xgv : r0;
        r1 = (lane == 1) ? r1 + xgv : r1;
        r2 = (lane == 2) ? r2 + xgv : r2;
        r3 = (lane == 3) ? r3 + xgv : r3;

        // butterfly: afterwards EVERY lane holds all four complete gate sums
#pragma unroll
        for (int off = 16; off; off >>= 1) {
            r0 += __shfl_xor_sync(0xffffffffu, r0, off);
            r1 += __shfl_xor_sync(0xffffffffu, r1, off);
            r2 += __shfl_xor_sync(0xffffffffu, r2, off);
            r3 += __shfl_xor_sync(0xffffffffu, r3, off);
        }

        // all-lane activations: no broadcast shfls, no divergence, 4-way ILP
        float gi = fast_sig(r0);
        float gf = fast_sig(r1);
        float gg = fast_tanh(r2);
        float go = fast_sig(r3);
        c = gf * c + gi * gg;
        float hv = go * fast_tanh(c);

        // aggregate the CTA's 8 h values, publish each replica-chunk as ONE
        // 16B store (all-or-nothing visibility for consumers)
        if (lane == 0) s_h[t & 1][w] = hv;
        __syncthreads();
        if (tid < 2 * NCOPY) {
            int rep = tid >> 1, ch = tid & 1;
            float4 val = *(float4*)&s_h[t & 1][ch * 4];
            float* dst = (float*)g_hsA + (size_t)rep * COPYSZ
                       + (size_t)t * HH + blockIdx.x * 8 + ch * 4;
            st_vol4(dst, val);
        }

        // prefetch next step's xg (gate on tile flag at 128-step boundaries)
        int tn = t + 1;
        if (tn < TM1 && lane < 4) {
            if ((tn & 127) == 0) wait_flag(&g_xgflag[tn >> 7]);
            xgv = g_xg[(size_t)tn * G4 + lane * HH + j];
        }
    }
}

// ---------------- fused persistent kernel ------------------------------------
__global__ __launch_bounds__(256, 1) void k_main(
    const float* __restrict__ W_ih,
    const float* __restrict__ W_hh,
    const float* __restrict__ W_out,
    const float* __restrict__ b_out,
    float* __restrict__ out)
{
    if (blockIdx.x < NLSTM) lstm_role(W_hh);
    else                    helper_role(W_ih, W_out, b_out, out);
}

// ---------------- launch ------------------------------------------------------
extern "C" void kernel_launch(void* const* d_in, const int* in_sizes, int n_in,
                              void* d_out, int out_size) {
    const int*   x     = (const int*)d_in[0];
    const float* table = (const float*)d_in[1];
    const float* W_ih  = (const float*)d_in[2];
    const float* W_hh  = (const float*)d_in[3];
    const float* b_ih  = (const float*)d_in[4];
    const float* b_hh  = (const float*)d_in[5];
    const float* W_out = (const float*)d_in[6];
    const float* b_out = (const float*)d_in[7];
    float* out = (float*)d_out;
    (void)in_sizes; (void)n_in; (void)out_size;

    k_gather<<<TT, 256>>>(x, table);            // gather + 8-replica canary + ctrl reset
    k_bias<<<G4 / 8, 256>>>(W_ih, b_ih, b_hh);
    k_main<<<NLSTM + NHELP, 256>>>(W_ih, W_hh, W_out, b_out, out);
}

// round 14
// speedup vs baseline: 1.5377x; 1.0021x over previous
#include <cuda_runtime.h>
#include <cstdint>

// Problem constants
#define TT    4096     // sequence length T
#define TM1   4095     // T-1 steps
#define EE    512      // embedding dim E
#define HH    1024     // hidden dim H
#define G4    4096     // 4*H
#define CC    1221     // output classes C
#define NLSTM 128      // recurrence CTAs
#define NHELP 20       // helper CTAs (GEMM overlap)
#define NCOPY 8        // h replica count — CONFIRMED optimum

#define XG_MT 32       // xg M tiles (4095 -> 32x128)
#define XG_NT 32       // xg N tiles (4096/128)
#define XG_TILES (XG_MT * XG_NT)
#define OUT_MT 32
#define OUT_NT 10      // ceil(1221/128)
#define OUT_TILES (OUT_MT * OUT_NT)

typedef unsigned long long u64;

#define CANARY 0x7fc0deadu   // qNaN payload: h in (-1,1) can never equal it
#define COPYSZ ((size_t)TM1 * HH)

// ---------------- scratch (static device globals; no allocation allowed) ----
__device__ float    g_emb[(size_t)TT * EE];        // gathered embeddings  (8 MB)
__device__ float    g_bias4h[G4];                  // b_ih + b_hh + last@W_ih[:,E:]
__device__ float    g_xg[(size_t)TM1 * G4];        // input gates (67 MB, JIT by helpers)
__device__ float    g_hsA[NCOPY * COPYSZ];         // hidden states, 8 replicas (134 MB)
__device__ unsigned g_work;                        // helper work-steal counter
__device__ unsigned g_xgcnt[XG_MT];                // completed N-tiles per xg M-tile
__device__ unsigned g_xgflag[XG_MT];               // xg M-tile ready flags

// ---------------- helpers ---------------------------------------------------
__device__ __forceinline__ u64 fma2(u64 a, u64 b, u64 c) {
    u64 d;
    asm("fma.rn.f32x2 %0, %1, %2, %3;" : "=l"(d) : "l"(a), "l"(b), "l"(c));
    return d;
}
__device__ __forceinline__ u64 pack2(float lo, float hi) {
    u64 r;
    asm("mov.b64 %0, {%1, %2};" : "=l"(r) : "f"(lo), "f"(hi));
    return r;
}
__device__ __forceinline__ float2 unpack2(u64 v) {
    float2 r;
    asm("mov.b64 {%0, %1}, %2;" : "=f"(r.x), "=f"(r.y) : "l"(v));
    return r;
}
__device__ __forceinline__ uint4 ld_vol4(const void* p) {
    uint4 v;
    asm volatile("ld.volatile.global.v4.u32 {%0,%1,%2,%3}, [%4];"
                 : "=r"(v.x), "=r"(v.y), "=r"(v.z), "=r"(v.w)
                 : "l"(p) : "memory");
    return v;
}
__device__ __forceinline__ void st_vol4(float* p, float4 v) {
    asm volatile("st.volatile.global.v4.f32 [%0], {%1,%2,%3,%4};"
                 :: "l"(p), "f"(v.x), "f"(v.y), "f"(v.z), "f"(v.w) : "memory");
}
__device__ __forceinline__ bool bad4(uint4 v) {
    return (v.x == CANARY) | (v.y == CANARY) | (v.z == CANARY) | (v.w == CANARY);
}
__device__ __forceinline__ unsigned ld_acq(const unsigned* p) {
    unsigned v;
    asm volatile("ld.acquire.gpu.global.u32 %0, [%1];" : "=r"(v) : "l"(p) : "memory");
    return v;
}
__device__ __forceinline__ void wait_flag(const unsigned* p) {
    while (ld_acq(p) == 0u) { }
}
__device__ __forceinline__ float fast_sig(float x) {      // exact: 1/(1+e^-x)
    return __fdividef(1.f, 1.f + __expf(-x));
}
__device__ __forceinline__ float fast_tanh(float x) {     // exact: 2*sig(2x)-1
    return __fdividef(2.f, 1.f + __expf(-2.f * x)) - 1.f;
}

// ---------------- gather + replica canary fill + control reset ---------------
__global__ void k_gather(const int* __restrict__ x, const float* __restrict__ tab) {
    int t   = blockIdx.x;
    int tid = threadIdx.x;
    if (blockIdx.x == 0) {
        if (tid == 0) g_work = 0u;
        if (tid < XG_MT) { g_xgcnt[tid] = 0u; g_xgflag[tid] = 0u; }
    }
    if (tid < 128) {
        int row = x[t];
        float4 v = *(const float4*)(tab + (size_t)row * EE + tid * 4);
        *(float4*)(g_emb + (size_t)t * EE + tid * 4) = v;
    }
    size_t i = (size_t)blockIdx.x * 256 + tid;          // uint4 index within a copy
    if (i < COPYSZ / 4) {
        uint4 c4 = make_uint4(CANARY, CANARY, CANARY, CANARY);
#pragma unroll
        for (int c = 0; c < NCOPY; c++)
            *(uint4*)((unsigned*)g_hsA + c * COPYSZ + i * 4) = c4;
    }
}

// ---------------- bias vector: b_ih + b_hh + last_emb @ W_ih[:, E:].T --------
__global__ void k_bias(const float* __restrict__ W_ih,
                       const float* __restrict__ b_ih,
                       const float* __restrict__ b_hh) {
    int w = threadIdx.x >> 5, lane = threadIdx.x & 31;
    int g = blockIdx.x * 8 + w;
    const float* wrow = W_ih + (size_t)g * (2 * EE) + EE;
    const float* le   = g_emb + (size_t)(TT - 1) * EE;
    float s = 0.f;
#pragma unroll
    for (int i = 0; i < 4; i++) {
        float4 a = *(const float4*)(wrow + i * 128 + lane * 4);
        float4 b = *(const float4*)(le   + i * 128 + lane * 4);
        s += a.x * b.x + a.y * b.y + a.z * b.z + a.w * b.w;
    }
#pragma unroll
    for (int off = 16; off; off >>= 1) s += __shfl_xor_sync(0xffffffffu, s, off);
    if (lane == 0) g_bias4h[g] = s + b_ih[g] + b_hh[g];
}

// ---------------- one 128x128 SGEMM tile: C = A * B^T + bias -----------------
// POLLA: A elements are NaN-canary dataflow values (retry until written).
template<bool POLLA>
__device__ void sgemm_tile(
    const float* A, int lda,
    const float* __restrict__ B, int ldb,
    const float* __restrict__ bias,
    float* C, int ldc,
    int M, int N, int K, int row0, int col0)
{
    __shared__ __align__(16) float As[16][128];
    __shared__ __align__(16) float Bs[16][128];
    int tid = threadIdx.x;
    int tx = tid & 15, ty = tid >> 4;

    u64 acc[8][4];
#pragma unroll
    for (int m = 0; m < 8; m++)
#pragma unroll
        for (int n2 = 0; n2 < 4; n2++) acc[m][n2] = 0ull;

    for (int k0 = 0; k0 < K; k0 += 16) {
#pragma unroll
        for (int li = tid; li < 512; li += 256) {
            int r = li >> 2, c4 = (li & 3) << 2;
            float4 v = make_float4(0.f, 0.f, 0.f, 0.f);
            int gr = row0 + r;
            if (gr < M) {
                const void* src = A + (size_t)gr * lda + k0 + c4;
                if (POLLA) {
                    uint4 u;
                    do { u = ld_vol4(src); } while (bad4(u));
                    v = *(float4*)&u;
                } else {
                    v = *(const float4*)src;
                }
            }
            As[c4][r] = v.x; As[c4 + 1][r] = v.y; As[c4 + 2][r] = v.z; As[c4 + 3][r] = v.w;
            float4 wv = make_float4(0.f, 0.f, 0.f, 0.f);
            int gn = col0 + r;
            if (gn < N) wv = *(const float4*)(B + (size_t)gn * ldb + k0 + c4);
            Bs[c4][r] = wv.x; Bs[c4 + 1][r] = wv.y; Bs[c4 + 2][r] = wv.z; Bs[c4 + 3][r] = wv.w;
        }
        __syncthreads();
#pragma unroll
        for (int k = 0; k < 16; k++) {
            float4 a0 = *(const float4*)&As[k][ty * 8];
            float4 a1 = *(const float4*)&As[k][ty * 8 + 4];
            ulonglong2 b0 = *(const ulonglong2*)&Bs[k][tx * 8];
            ulonglong2 b1 = *(const ulonglong2*)&Bs[k][tx * 8 + 4];
            float av[8] = {a0.x, a0.y, a0.z, a0.w, a1.x, a1.y, a1.z, a1.w};
            u64 bv[4] = {b0.x, b0.y, b1.x, b1.y};
#pragma unroll
            for (int m = 0; m < 8; m++) {
                u64 am = pack2(av[m], av[m]);
#pragma unroll
                for (int n2 = 0; n2 < 4; n2++)
                    acc[m][n2] = fma2(am, bv[n2], acc[m][n2]);
            }
        }
        __syncthreads();
    }
#pragma unroll
    for (int m = 0; m < 8; m++) {
        int gr = row0 + ty * 8 + m;
        if (gr >= M) continue;
#pragma unroll
        for (int n2 = 0; n2 < 4; n2++) {
            float2 s = unpack2(acc[m][n2]);
            int gc = col0 + tx * 8 + n2 * 2;
            if (gc < N)     C[(size_t)gr * ldc + gc]     = s.x + bias[gc];
            if (gc + 1 < N) C[(size_t)gr * ldc + gc + 1] = s.y + bias[gc + 1];
        }
    }
}

// ---------------- helper role: JIT xg GEMM, then trailing out GEMM -----------
__device__ void helper_role(const float* __restrict__ W_ih,
                            const float* __restrict__ W_out,
                            const float* __restrict__ b_out,
                            float* __restrict__ out) {
    __shared__ unsigned s_item;
    int tid = threadIdx.x;
    for (;;) {
        if (tid == 0) s_item = atomicAdd(&g_work, 1u);
        __syncthreads();
        unsigned item = s_item;
        __syncthreads();
        if (item < XG_TILES) {
            // xg tile, M-tile-major so rows appear in consumption order
            int mt = item >> 5, nt = item & 31;
            sgemm_tile<false>(g_emb, EE, W_ih, 2 * EE, g_bias4h,
                              g_xg, G4, TM1, G4, EE, mt * 128, nt * 128);
            __threadfence();
            __syncthreads();
            if (tid == 0) {
                unsigned old;
                asm volatile("atom.acq_rel.gpu.global.add.u32 %0, [%1], 1;"
                             : "=r"(old) : "l"(&g_xgcnt[mt]) : "memory");
                if (old == XG_NT - 1)
                    asm volatile("st.release.gpu.global.u32 [%0], %1;"
                                 :: "l"(&g_xgflag[mt]), "r"(1u) : "memory");
            }
            __syncthreads();
        } else if (item < XG_TILES + OUT_TILES) {
            // out tile; A loads canary-poll h rows (self-throttles to frontier)
            int idx = (int)item - XG_TILES;
            int mt = idx / OUT_NT, nt = idx % OUT_NT;
            const float* hsrc = g_hsA + (size_t)(mt & (NCOPY - 1)) * COPYSZ;
            sgemm_tile<true>(hsrc, HH, W_out, HH, b_out,
                             out, CC, TM1, CC, HH, mt * 128, nt * 128);
            __syncthreads();
        } else {
            break;
        }
    }
}

// ---------------- recurrence role (R13 + dual-outstanding poll retry) --------
__device__ void lstm_role(const float* __restrict__ W_hh) {
    __shared__ __align__(16) float h_s[2][HH];
    __shared__ __align__(16) float s_h[2][8];      // per-warp h staging (double buf)
    int tid = threadIdx.x;
    int w = tid >> 5, lane = tid & 31;
    int j = blockIdx.x * 8 + w;
    const float* mycopy = g_hsA + (size_t)(blockIdx.x & (NCOPY - 1)) * COPYSZ;

    // This warp's W_hh rows in registers: 4 gates x 32 k per lane (f32x2 pairs)
    ulonglong2 wr[4][8];
#pragma unroll
    for (int g = 0; g < 4; g++) {
        const float* base = W_hh + (size_t)(g * HH + j) * HH + lane * 4;
#pragma unroll
        for (int i = 0; i < 8; i++)
            wr[g][i] = *(const ulonglong2*)(base + i * 128);
    }

    float c = 0.f;
    float xgv = 0.f;
    if (lane < 4) {                       // t = 0 prefetch (gated on xg tile 0)
        wait_flag(&g_xgflag[0]);
        xgv = g_xg[(size_t)lane * HH + j];
    }

    for (int t = 0; t < TM1; t++) {
        float* buf = h_s[t & 1];

        // stage own 16B chunk of h_{t-1} from my replica.
        // Dual-outstanding retry: two volatile loads in flight -> sampling
        // period ~RT/2, cutting the poll-phase tail that gates every step.
        if (t == 0) {
            *(float4*)&buf[tid * 4] = make_float4(0.f, 0.f, 0.f, 0.f);
        } else {
            const void* src = mycopy + (size_t)(t - 1) * HH + tid * 4;
            uint4 v = ld_vol4(src);
            if (bad4(v)) {
                uint4 a = ld_vol4(src);
                uint4 b = ld_vol4(src);
                for (;;) {
                    if (!bad4(a)) { v = a; break; }
                    a = b;
                    b = ld_vol4(src);
                }
            }
            *(uint4*)&buf[tid * 4] = v;
        }
        __syncthreads();

        // 4 gate dot products over K=1024, f32x2 FMAs
        u64 acc[4] = {0ull, 0ull, 0ull, 0ull};
#pragma unroll
        for (int i = 0; i < 8; i++) {
            ulonglong2 h2 = *(const ulonglong2*)&buf[i * 128 + lane * 4];
#pragma unroll
            for (int g = 0; g < 4; g++) {
                acc[g] = fma2(wr[g][i].x, h2.x, acc[g]);
                acc[g] = fma2(wr[g][i].y, h2.y, acc[g]);
            }
        }
        float r0, r1, r2, r3;
        { float2 s = unpack2(acc[0]); r0 = s.x + s.y; }
        { float2 s = unpack2(acc[1]); r1 = s.x + s.y; }
        { float2 s = unpack2(acc[2]); r2 = s.x + s.y; }
        { float2 s = unpack2(acc[3]); r3 = s.x + s.y; }

        // pre-reduce xg injection: the butterfly sums it in exactly once
        r0 = (lane == 0) ? r0 + xgv : r0;
        r1 = (lane == 1) ? r1 + xgv : r1;
        r2 = (lane == 2) ? r2 + xgv : r2;
        r3 = (lane == 3) ? r3 + xgv : r3;

        // butterfly: afterwards EVERY lane holds all four complete gate sums
#pragma unroll
        for (int off = 16; off; off >>= 1) {
            r0 += __shfl_xor_sync(0xffffffffu, r0, off);
            r1 += __shfl_xor_sync(0xffffffffu, r1, off);
            r2 += __shfl_xor_sync(0xffffffffu, r2, off);
            r3 += __shfl_xor_sync(0xffffffffu, r3, off);
        }

        // all-lane activations: no broadcast shfls, no divergence, 4-way ILP
        float gi = fast_sig(r0);
        float gf = fast_sig(r1);
        float gg = fast_tanh(r2);
        float go = fast_sig(r3);
        c = gf * c + gi * gg;
        float hv = go * fast_tanh(c);

        // aggregate the CTA's 8 h values, publish each replica-chunk as ONE
        // 16B store (all-or-nothing visibility for consumers)
        if (lane == 0) s_h[t & 1][w] = hv;
        __syncthreads();
        if (tid < 2 * NCOPY) {
            int rep = tid >> 1, ch = tid & 1;
            float4 val = *(float4*)&s_h[t & 1][ch * 4];
            float* dst = (float*)g_hsA + (size_t)rep * COPYSZ
                       + (size_t)t * HH + blockIdx.x * 8 + ch * 4;
            st_vol4(dst, val);
        }

        // prefetch next step's xg (gate on tile flag at 128-step boundaries)
        int tn = t + 1;
        if (tn < TM1 && lane < 4) {
            if ((tn & 127) == 0) wait_flag(&g_xgflag[tn >> 7]);
            xgv = g_xg[(size_t)tn * G4 + lane * HH + j];
        }
    }
}

// ---------------- fused persistent kernel ------------------------------------
__global__ __launch_bounds__(256, 1) void k_main(
    const float* __restrict__ W_ih,
    const float* __restrict__ W_hh,
    const float* __restrict__ W_out,
    const float* __restrict__ b_out,
    float* __restrict__ out)
{
    if (blockIdx.x < NLSTM) lstm_role(W_hh);
    else                    helper_role(W_ih, W_out, b_out, out);
}

// ---------------- launch ------------------------------------------------------
extern "C" void kernel_launch(void* const* d_in, const int* in_sizes, int n_in,
                              void* d_out, int out_size) {
    const int*   x     = (const int*)d_in[0];
    const float* table = (const float*)d_in[1];
    const float* W_ih  = (const float*)d_in[2];
    const float* W_hh  = (const float*)d_in[3];
    const float* b_ih  = (const float*)d_in[4];
    const float* b_hh  = (const float*)d_in[5];
    const float* W_out = (const float*)d_in[6];
    const float* b_out = (const float*)d_in[7];
    float* out = (float*)d_out;
    (void)in_sizes; (void)n_in; (void)out_size;

    k_gather<<<TT, 256>>>(x, table);            // gather + 8-replica canary + ctrl reset
    k_bias<<<G4 / 8, 256>>>(W_ih, b_ih, b_hh);
    k_main<<<NLSTM + NHELP, 256>>>(W_ih, W_hh, W_out, b_out, out);
}

// round 15
// speedup vs baseline: 1.5435x; 1.0037x over previous
#include <cuda_runtime.h>
#include <cstdint>

// Problem constants
#define TT    4096     // sequence length T
#define TM1   4095     // T-1 steps
#define EE    512      // embedding dim E
#define HH    1024     // hidden dim H
#define G4    4096     // 4*H
#define CC    1221     // output classes C
#define NLSTM 128      // recurrence CTAs
#define NHELP 20       // helper CTAs (GEMM overlap)
#define NCOPY 8        // h replica count — CONFIRMED optimum

#define XG_MT 32       // xg M tiles (4095 -> 32x128)
#define XG_NT 32       // xg N tiles (4096/128)
#define XG_TILES (XG_MT * XG_NT)
#define OUT_MT 32
#define OUT_NT 10      // ceil(1221/128)
#define OUT_TILES (OUT_MT * OUT_NT)

typedef unsigned long long u64;

#define CANARY 0x7fc0deadu   // qNaN payload: h in (-1,1) can never equal it
#define COPYSZ ((size_t)TM1 * HH)

// ---------------- scratch (static device globals; no allocation allowed) ----
__device__ float    g_emb[(size_t)TT * EE];        // gathered embeddings  (8 MB)
__device__ float    g_bias4h[G4];                  // b_ih + b_hh + last@W_ih[:,E:]
__device__ float    g_xg[(size_t)TM1 * G4];        // input gates (67 MB, JIT by helpers)
__device__ float    g_hsA[NCOPY * COPYSZ];         // hidden states, 8 replicas (134 MB)
__device__ unsigned g_work;                        // helper work-steal counter
__device__ unsigned g_xgcnt[XG_MT];                // completed N-tiles per xg M-tile
__device__ unsigned g_xgflag[XG_MT];               // xg M-tile ready flags

// ---------------- helpers ---------------------------------------------------
__device__ __forceinline__ u64 fma2(u64 a, u64 b, u64 c) {
    u64 d;
    asm("fma.rn.f32x2 %0, %1, %2, %3;" : "=l"(d) : "l"(a), "l"(b), "l"(c));
    return d;
}
__device__ __forceinline__ u64 pack2(float lo, float hi) {
    u64 r;
    asm("mov.b64 %0, {%1, %2};" : "=l"(r) : "f"(lo), "f"(hi));
    return r;
}
__device__ __forceinline__ float2 unpack2(u64 v) {
    float2 r;
    asm("mov.b64 {%0, %1}, %2;" : "=f"(r.x), "=f"(r.y) : "l"(v));
    return r;
}
__device__ __forceinline__ uint4 ld_vol4(const void* p) {
    uint4 v;
    asm volatile("ld.volatile.global.v4.u32 {%0,%1,%2,%3}, [%4];"
                 : "=r"(v.x), "=r"(v.y), "=r"(v.z), "=r"(v.w)
                 : "l"(p) : "memory");
    return v;
}
__device__ __forceinline__ void st_vol4(float* p, float4 v) {
    asm volatile("st.volatile.global.v4.f32 [%0], {%1,%2,%3,%4};"
                 :: "l"(p), "f"(v.x), "f"(v.y), "f"(v.z), "f"(v.w) : "memory");
}
__device__ __forceinline__ bool bad4(uint4 v) {
    return (v.x == CANARY) | (v.y == CANARY) | (v.z == CANARY) | (v.w == CANARY);
}
__device__ __forceinline__ unsigned ld_acq(const unsigned* p) {
    unsigned v;
    asm volatile("ld.acquire.gpu.global.u32 %0, [%1];" : "=r"(v) : "l"(p) : "memory");
    return v;
}
__device__ __forceinline__ void wait_flag(const unsigned* p) {
    while (ld_acq(p) == 0u) { }
}
__device__ __forceinline__ void sleep_ns(unsigned n) {
    asm volatile("nanosleep.u32 %0;" :: "r"(n));
}
__device__ __forceinline__ float fast_sig(float x) {      // exact: 1/(1+e^-x)
    return __fdividef(1.f, 1.f + __expf(-x));
}
__device__ __forceinline__ float fast_tanh(float x) {     // exact: 2*sig(2x)-1
    return __fdividef(2.f, 1.f + __expf(-2.f * x)) - 1.f;
}

// ---------------- gather + replica canary fill + control reset ---------------
__global__ void k_gather(const int* __restrict__ x, const float* __restrict__ tab) {
    int t   = blockIdx.x;
    int tid = threadIdx.x;
    if (blockIdx.x == 0) {
        if (tid == 0) g_work = 0u;
        if (tid < XG_MT) { g_xgcnt[tid] = 0u; g_xgflag[tid] = 0u; }
    }
    if (tid < 128) {
        int row = x[t];
        float4 v = *(const float4*)(tab + (size_t)row * EE + tid * 4);
        *(float4*)(g_emb + (size_t)t * EE + tid * 4) = v;
    }
    size_t i = (size_t)blockIdx.x * 256 + tid;          // uint4 index within a copy
    if (i < COPYSZ / 4) {
        uint4 c4 = make_uint4(CANARY, CANARY, CANARY, CANARY);
#pragma unroll
        for (int c = 0; c < NCOPY; c++)
            *(uint4*)((unsigned*)g_hsA + c * COPYSZ + i * 4) = c4;
    }
}

// ---------------- bias vector: b_ih + b_hh + last_emb @ W_ih[:, E:].T --------
__global__ void k_bias(const float* __restrict__ W_ih,
                       const float* __restrict__ b_ih,
                       const float* __restrict__ b_hh) {
    int w = threadIdx.x >> 5, lane = threadIdx.x & 31;
    int g = blockIdx.x * 8 + w;
    const float* wrow = W_ih + (size_t)g * (2 * EE) + EE;
    const float* le   = g_emb + (size_t)(TT - 1) * EE;
    float s = 0.f;
#pragma unroll
    for (int i = 0; i < 4; i++) {
        float4 a = *(const float4*)(wrow + i * 128 + lane * 4);
        float4 b = *(const float4*)(le   + i * 128 + lane * 4);
        s += a.x * b.x + a.y * b.y + a.z * b.z + a.w * b.w;
    }
#pragma unroll
    for (int off = 16; off; off >>= 1) s += __shfl_xor_sync(0xffffffffu, s, off);
    if (lane == 0) g_bias4h[g] = s + b_ih[g] + b_hh[g];
}

// ---------------- one 128x128 SGEMM tile: C = A * B^T + bias -----------------
// POLLA: A elements are NaN-canary dataflow values (retry until written).
template<bool POLLA>
__device__ void sgemm_tile(
    const float* A, int lda,
    const float* __restrict__ B, int ldb,
    const float* __restrict__ bias,
    float* C, int ldc,
    int M, int N, int K, int row0, int col0)
{
    __shared__ __align__(16) float As[16][128];
    __shared__ __align__(16) float Bs[16][128];
    int tid = threadIdx.x;
    int tx = tid & 15, ty = tid >> 4;

    u64 acc[8][4];
#pragma unroll
    for (int m = 0; m < 8; m++)
#pragma unroll
        for (int n2 = 0; n2 < 4; n2++) acc[m][n2] = 0ull;

    for (int k0 = 0; k0 < K; k0 += 16) {
#pragma unroll
        for (int li = tid; li < 512; li += 256) {
            int r = li >> 2, c4 = (li & 3) << 2;
            float4 v = make_float4(0.f, 0.f, 0.f, 0.f);
            int gr = row0 + r;
            if (gr < M) {
                const void* src = A + (size_t)gr * lda + k0 + c4;
                if (POLLA) {
                    uint4 u;
                    do { u = ld_vol4(src); } while (bad4(u));
                    v = *(float4*)&u;
                } else {
                    v = *(const float4*)src;
                }
            }
            As[c4][r] = v.x; As[c4 + 1][r] = v.y; As[c4 + 2][r] = v.z; As[c4 + 3][r] = v.w;
            float4 wv = make_float4(0.f, 0.f, 0.f, 0.f);
            int gn = col0 + r;
            if (gn < N) wv = *(const float4*)(B + (size_t)gn * ldb + k0 + c4);
            Bs[c4][r] = wv.x; Bs[c4 + 1][r] = wv.y; Bs[c4 + 2][r] = wv.z; Bs[c4 + 3][r] = wv.w;
        }
        __syncthreads();
#pragma unroll
        for (int k = 0; k < 16; k++) {
            float4 a0 = *(const float4*)&As[k][ty * 8];
            float4 a1 = *(const float4*)&As[k][ty * 8 + 4];
            ulonglong2 b0 = *(const ulonglong2*)&Bs[k][tx * 8];
            ulonglong2 b1 = *(const ulonglong2*)&Bs[k][tx * 8 + 4];
            float av[8] = {a0.x, a0.y, a0.z, a0.w, a1.x, a1.y, a1.z, a1.w};
            u64 bv[4] = {b0.x, b0.y, b1.x, b1.y};
#pragma unroll
            for (int m = 0; m < 8; m++) {
                u64 am = pack2(av[m], av[m]);
#pragma unroll
                for (int n2 = 0; n2 < 4; n2++)
                    acc[m][n2] = fma2(am, bv[n2], acc[m][n2]);
            }
        }
        __syncthreads();
    }
#pragma unroll
    for (int m = 0; m < 8; m++) {
        int gr = row0 + ty * 8 + m;
        if (gr >= M) continue;
#pragma unroll
        for (int n2 = 0; n2 < 4; n2++) {
            float2 s = unpack2(acc[m][n2]);
            int gc = col0 + tx * 8 + n2 * 2;
            if (gc < N)     C[(size_t)gr * ldc + gc]     = s.x + bias[gc];
            if (gc + 1 < N) C[(size_t)gr * ldc + gc + 1] = s.y + bias[gc + 1];
        }
    }
}

// ---------------- helper role: JIT xg GEMM, then trailing out GEMM -----------
__device__ void helper_role(const float* __restrict__ W_ih,
                            const float* __restrict__ W_out,
                            const float* __restrict__ b_out,
                            float* __restrict__ out) {
    __shared__ unsigned s_item;
    int tid = threadIdx.x;
    for (;;) {
        if (tid == 0) s_item = atomicAdd(&g_work, 1u);
        __syncthreads();
        unsigned item = s_item;
        __syncthreads();
        if (item < XG_TILES) {
            // xg tile, M-tile-major so rows appear in consumption order
            int mt = item >> 5, nt = item & 31;
            sgemm_tile<false>(g_emb, EE, W_ih, 2 * EE, g_bias4h,
                              g_xg, G4, TM1, G4, EE, mt * 128, nt * 128);
            __threadfence();
            __syncthreads();
            if (tid == 0) {
                unsigned old;
                asm volatile("atom.acq_rel.gpu.global.add.u32 %0, [%1], 1;"
                             : "=r"(old) : "l"(&g_xgcnt[mt]) : "memory");
                if (old == XG_NT - 1)
                    asm volatile("st.release.gpu.global.u32 [%0], %1;"
                                 :: "l"(&g_xgflag[mt]), "r"(1u) : "memory");
            }
            __syncthreads();
        } else if (item < XG_TILES + OUT_TILES) {
            // out tile. Steps complete in t-order, so gate the whole tile on
            // its LAST row with a sleep-throttled sentinel poll: after that
            // the inner tight polls hit ready data on the first probe, and
            // helper poll-flood never touches the recurrence frontier.
            int idx = (int)item - XG_TILES;
            int mt = idx / OUT_NT, nt = idx % OUT_NT;
            const float* hsrc = g_hsA + (size_t)(mt & (NCOPY - 1)) * COPYSZ;
            int last_row = mt * 128 + 127; if (last_row > TM1 - 1) last_row = TM1 - 1;
            if (tid == 0) {
                const float* gp0 = hsrc + (size_t)last_row * HH;          // cols 0..3
                const float* gp1 = hsrc + (size_t)last_row * HH + HH - 4; // cols 1020..1023
                uint4 u0 = ld_vol4(gp0), u1 = ld_vol4(gp1);
                while (bad4(u0) || bad4(u1)) {
                    sleep_ns(2000);
                    u0 = ld_vol4(gp0);
                    u1 = ld_vol4(gp1);
                }
            }
            __syncthreads();
            sgemm_tile<true>(hsrc, HH, W_out, HH, b_out,
                             out, CC, TM1, CC, HH, mt * 128, nt * 128);
            __syncthreads();
        } else {
            break;
        }
    }
}

// ---------------- recurrence role (byte-identical to R14 winner) -------------
__device__ void lstm_role(const float* __restrict__ W_hh) {
    __shared__ __align__(16) float h_s[2][HH];
    __shared__ __align__(16) float s_h[2][8];      // per-warp h staging (double buf)
    int tid = threadIdx.x;
    int w = tid >> 5, lane = tid & 31;
    int j = blockIdx.x * 8 + w;
    const float* mycopy = g_hsA + (size_t)(blockIdx.x & (NCOPY - 1)) * COPYSZ;

    // This warp's W_hh rows in registers: 4 gates x 32 k per lane (f32x2 pairs)
    ulonglong2 wr[4][8];
#pragma unroll
    for (int g = 0; g < 4; g++) {
        const float* base = W_hh + (size_t)(g * HH + j) * HH + lane * 4;
#pragma unroll
        for (int i = 0; i < 8; i++)
            wr[g][i] = *(const ulonglong2*)(base + i * 128);
    }

    float c = 0.f;
    float xgv = 0.f;
    if (lane < 4) {                       // t = 0 prefetch (gated on xg tile 0)
        wait_flag(&g_xgflag[0]);
        xgv = g_xg[(size_t)lane * HH + j];
    }

    for (int t = 0; t < TM1; t++) {
        float* buf = h_s[t & 1];

        // stage own 16B chunk of h_{t-1} from my replica.
        // Dual-outstanding retry: two volatile loads in flight -> sampling
        // period ~RT/2, cutting the poll-phase tail that gates every step.
        if (t == 0) {
            *(float4*)&buf[tid * 4] = make_float4(0.f, 0.f, 0.f, 0.f);
        } else {
            const void* src = mycopy + (size_t)(t - 1) * HH + tid * 4;
            uint4 v = ld_vol4(src);
            if (bad4(v)) {
                uint4 a = ld_vol4(src);
                uint4 b = ld_vol4(src);
                for (;;) {
                    if (!bad4(a)) { v = a; break; }
                    a = b;
                    b = ld_vol4(src);
                }
            }
            *(uint4*)&buf[tid * 4] = v;
        }
        __syncthreads();

        // 4 gate dot products over K=1024, f32x2 FMAs
        u64 acc[4] = {0ull, 0ull, 0ull, 0ull};
#pragma unroll
        for (int i = 0; i < 8; i++) {
            ulonglong2 h2 = *(const ulonglong2*)&buf[i * 128 + lane * 4];
#pragma unroll
            for (int g = 0; g < 4; g++) {
                acc[g] = fma2(wr[g][i].x, h2.x, acc[g]);
                acc[g] = fma2(wr[g][i].y, h2.y, acc[g]);
            }
        }
        float r0, r1, r2, r3;
        { float2 s = unpack2(acc[0]); r0 = s.x + s.y; }
        { float2 s = unpack2(acc[1]); r1 = s.x + s.y; }
        { float2 s = unpack2(acc[2]); r2 = s.x + s.y; }
        { float2 s = unpack2(acc[3]); r3 = s.x + s.y; }

        // pre-reduce xg injection: the butterfly sums it in exactly once
        r0 = (lane == 0) ? r0 + xgv : r0;
        r1 = (lane == 1) ? r1 + xgv : r1;
        r2 = (lane == 2) ? r2 + xgv : r2;
        r3 = (lane == 3) ? r3 + xgv : r3;

        // butterfly: afterwards EVERY lane holds all four complete gate sums
#pragma unroll
        for (int off = 16; off; off >>= 1) {
            r0 += __shfl_xor_sync(0xffffffffu, r0, off);
            r1 += __shfl_xor_sync(0xffffffffu, r1, off);
            r2 += __shfl_xor_sync(0xffffffffu, r2, off);
            r3 += __shfl_xor_sync(0xffffffffu, r3, off);
        }

        // all-lane activations: no broadcast shfls, no divergence, 4-way ILP
        float gi = fast_sig(r0);
        float gf = fast_sig(r1);
        float gg = fast_tanh(r2);
        float go = fast_sig(r3);
        c = gf * c + gi * gg;
        float hv = go * fast_tanh(c);

        // aggregate the CTA's 8 h values, publish each replica-chunk as ONE
        // 16B store (all-or-nothing visibility for consumers)
        if (lane == 0) s_h[t & 1][w] = hv;
        __syncthreads();
        if (tid < 2 * NCOPY) {
            int rep = tid >> 1, ch = tid & 1;
            float4 val = *(float4*)&s_h[t & 1][ch * 4];
            float* dst = (float*)g_hsA + (size_t)rep * COPYSZ
                       + (size_t)t * HH + blockIdx.x * 8 + ch * 4;
            st_vol4(dst, val);
        }

        // prefetch next step's xg (gate on tile flag at 128-step boundaries)
        int tn = t + 1;
        if (tn < TM1 && lane < 4) {
            if ((tn & 127) == 0) wait_flag(&g_xgflag[tn >> 7]);
            xgv = g_xg[(size_t)tn * G4 + lane * HH + j];
        }
    }
}

// ---------------- fused persistent kernel ------------------------------------
__global__ __launch_bounds__(256, 1) void k_main(
    const float* __restrict__ W_ih,
    const float* __restrict__ W_hh,
    const float* __restrict__ W_out,
    const float* __restrict__ b_out,
    float* __restrict__ out)
{
    if (blockIdx.x < NLSTM) lstm_role(W_hh);
    else                    helper_role(W_ih, W_out, b_out, out);
}

// ---------------- launch ------------------------------------------------------
extern "C" void kernel_launch(void* const* d_in, const int* in_sizes, int n_in,
                              void* d_out, int out_size) {
    const int*   x     = (const int*)d_in[0];
    const float* table = (const float*)d_in[1];
    const float* W_ih  = (const float*)d_in[2];
    const float* W_hh  = (const float*)d_in[3];
    const float* b_ih  = (const float*)d_in[4];
    const float* b_hh  = (const float*)d_in[5];
    const float* W_out = (const float*)d_in[6];
    const float* b_out = (const float*)d_in[7];
    float* out = (float*)d_out;
    (void)in_sizes; (void)n_in; (void)out_size;

    k_gather<<<TT, 256>>>(x, table);            // gather + 8-replica canary + ctrl reset
    k_bias<<<G4 / 8, 256>>>(W_ih, b_ih, b_hh);
    k_main<<<NLSTM + NHELP, 256>>>(W_ih, W_hh, W_out, b_out, out);
}